// round 5
// baseline (speedup 1.0000x reference)
#include <cuda_runtime.h>
#include <cuda_bf16.h>

// NCEAverage: out[b,k] = exp(dot(memory[idx'[b,k]], x[b]) / T) / Z
// idx'[b,0] = y[b];  Z = mean(out_unnorm) * N
// B=256, K=4096, D=128, N=1e6, T=0.07
//
// Single fused kernel: 1024 fully-resident blocks (<= 148 SMs * 8 blocks),
// each owns 2 units of 512 scores kept in SMEM; grid-wide software sync
// publishes the deterministic double-precision scale; scaled output written
// once. No norm kernel, no unnormalized DRAM round-trip.

#define B_SZ 256
#define K_SZ 4096
#define D_SZ 128
#define N_SZ 1000000
#define INV_T (1.0f / 0.07f)

#define WARPS 8
#define THREADS (WARPS * 32)          // 256
#define SPLIT 8                       // k-chunks per b
#define KCHUNK (K_SZ / SPLIT)         // 512
#define ITERS (KCHUNK / WARPS)        // 64 k's per warp per unit
#define NUNITS (B_SZ * SPLIT)         // 2048
#define NBLK (NUNITS / 2)             // 1024 blocks, 2 units each
#define UPB 2                         // units per block

__device__ float        g_partials[NBLK];
__device__ float        g_scale;
__device__ unsigned int g_ticket;     // zero-init; protocol self-resets
__device__ unsigned int g_release;
__device__ unsigned int g_done;

__global__ __launch_bounds__(THREADS, 8)
void nce_fused_kernel(const float* __restrict__ x,
                      const int* __restrict__ y,
                      const int* __restrict__ idx,
                      const float* __restrict__ memory,
                      float* __restrict__ out) {
    __shared__ float  sc[UPB][KCHUNK];   // 4 KB of unnormalized scores
    __shared__ float  ssum[WARPS];
    __shared__ double dsh[THREADS];
    __shared__ bool   s_last;

    const int tid  = threadIdx.x;
    const int lane = tid & 31;
    const int warp = tid >> 5;

    float wsum = 0.0f;

    // ---- Phase 1: gather + dot + exp for my 2 units ----
    #pragma unroll 1
    for (int uu = 0; uu < UPB; uu++) {
        const int u  = blockIdx.x * UPB + uu;
        const int b  = u >> 3;                    // SPLIT == 8
        const int k0 = (u & 7) * KCHUNK;

        const float4 xv = reinterpret_cast<const float4*>(x + b * D_SZ)[lane];
        const int* idx_b = idx + (size_t)b * K_SZ;

        #pragma unroll 1
        for (int i = 0; i < ITERS; i += 2) {
            const int k1 = k0 + warp + (i    ) * WARPS;
            const int k2 = k0 + warp + (i + 1) * WARPS;

            const int row1 = (k1 == 0) ? y[b] : idx_b[k1];  // slot 0 = positive
            const int row2 = idx_b[k2];

            const float4 w1 = reinterpret_cast<const float4*>(memory + (size_t)row1 * D_SZ)[lane];
            const float4 w2 = reinterpret_cast<const float4*>(memory + (size_t)row2 * D_SZ)[lane];

            float d1 = w1.x * xv.x + w1.y * xv.y + w1.z * xv.z + w1.w * xv.w;
            float d2 = w2.x * xv.x + w2.y * xv.y + w2.z * xv.z + w2.w * xv.w;

            #pragma unroll
            for (int s = 16; s > 0; s >>= 1) {
                d1 += __shfl_xor_sync(0xffffffffu, d1, s);
                d2 += __shfl_xor_sync(0xffffffffu, d2, s);
            }

            if (lane == 0) {
                const float s1 = __expf(d1 * INV_T);
                const float s2 = __expf(d2 * INV_T);
                sc[uu][k1 - k0] = s1;
                sc[uu][k2 - k0] = s2;
                wsum += s1 + s2;
            }
        }
    }

    // ---- Block partial (deterministic fixed order) ----
    if (lane == 0) ssum[warp] = wsum;
    __syncthreads();
    if (tid == 0) {
        float t = 0.0f;
        #pragma unroll
        for (int w = 0; w < WARPS; w++) t += ssum[w];
        g_partials[blockIdx.x] = t;
        __threadfence();
        const unsigned int tk = atomicAdd(&g_ticket, 1u);
        s_last = (tk == NBLK - 1);
    }
    __syncthreads();

    // ---- Last block: reduce 1024 partials in double (fixed tree) ----
    if (s_last) {
        double acc = 0.0;
        #pragma unroll
        for (int j = 0; j < NBLK / THREADS; j++)
            acc += (double)g_partials[tid + j * THREADS];
        dsh[tid] = acc;
        __syncthreads();
        for (int s = THREADS / 2; s > 0; s >>= 1) {
            if (tid < s) dsh[tid] += dsh[tid + s];
            __syncthreads();
        }
        if (tid == 0) {
            // Z = (sum / (B*K)) * N ; scale = 1/Z — double avoids fp32
            // overflow (sum ~ 1e31; sum * N would be inf in fp32).
            const double sum = dsh[0];
            g_scale = (float)(((double)B_SZ * (double)K_SZ) /
                              (sum * (double)N_SZ));
            g_ticket = 0u;              // reset for graph replay
            __threadfence();
            atomicExch(&g_release, 1u); // publish
        }
    }

    // ---- Grid-wide wait for the scale ----
    if (tid == 0) {
        while (atomicAdd(&g_release, 0u) == 0u) __nanosleep(64);
        __threadfence();   // acquire: make g_scale visible
    }
    __syncthreads();
    const float scale = *((volatile float*)&g_scale);

    // ---- Write scaled output (single 4 MiB coalesced write) ----
    #pragma unroll
    for (int uu = 0; uu < UPB; uu++) {
        const int u  = blockIdx.x * UPB + uu;
        const int b  = u >> 3;
        const int k0 = (u & 7) * KCHUNK;
        float* ob = out + (size_t)b * K_SZ + k0;
        ob[tid]           = sc[uu][tid]           * scale;
        ob[tid + THREADS] = sc[uu][tid + THREADS] * scale;
    }

    // ---- Reset release flag for next graph replay ----
    __syncthreads();
    if (tid == 0) {
        const unsigned int d = atomicAdd(&g_done, 1u);
        if (d == NBLK - 1) {           // last block out resets everything
            g_done = 0u;
            atomicExch(&g_release, 0u);
        }
    }
}

extern "C" void kernel_launch(void* const* d_in, const int* in_sizes, int n_in,
                              void* d_out, int out_size) {
    const float* x      = (const float*)d_in[0];
    const int*   y      = (const int*)d_in[1];
    const int*   idx    = (const int*)d_in[2];
    const float* memory = (const float*)d_in[3];
    float* out = (float*)d_out;

    nce_fused_kernel<<<NBLK, THREADS>>>(x, y, idx, memory, out);
}

// round 6
// speedup vs baseline: 1.1424x; 1.1424x over previous
#include <cuda_runtime.h>
#include <cuda_bf16.h>

// NCEAverage: out[b,k] = exp(dot(memory[idx'[b,k]], x[b]) / T) / Z
// idx'[b,0] = y[b];  Z = mean(out_unnorm) * N
// B=256, K=4096, D=128, N=1e6, T=0.07
//
// Scores kernel: 8 lanes per row, 4 rows per warp-iteration.
//  - each LDG.128 covers 4 full 128B lines (one per row) — full coalescing
//  - 3 shfl (xor 1,2,4) reduce all 4 rows at once (vs 5 per row before)
//  - 4 independent LDG in flight per lane
// Z finalized by the last-arriving block (ticket), then a separate tiny
// norm kernel scales the output (no grid-wide barrier: stragglers stay local).

#define B_SZ 256
#define K_SZ 4096
#define D_SZ 128
#define N_SZ 1000000
#define INV_T (1.0f / 0.07f)

#define WARPS 8
#define THREADS (WARPS * 32)
#define SPLIT 8                       // gridDim.y
#define KCHUNK (K_SZ / SPLIT)         // 512 k's per block
#define KPW (KCHUNK / WARPS)          // 64 k's per warp
#define RPI 4                         // rows per warp-iteration
#define NBLOCKS (B_SZ * SPLIT)        // 2048

__device__ float        g_partials[NBLOCKS];
__device__ float        g_scale;
__device__ unsigned int g_ticket;     // zero-init; last block resets

__global__ __launch_bounds__(THREADS, 5)
void nce_scores_kernel(const float* __restrict__ x,
                       const int* __restrict__ y,
                       const int* __restrict__ idx,
                       const float* __restrict__ memory,
                       float* __restrict__ out) {
    const int b    = blockIdx.x;
    const int lane = threadIdx.x & 31;
    const int warp = threadIdx.x >> 5;
    const int o    = lane & 7;        // octet position within row
    const int r    = lane >> 3;       // which of 4 rows this lane serves
    const int k0   = blockIdx.y * KCHUNK + warp * KPW;

    // x fragment for this lane: float4 j*8+o, j=0..3 (invariant per block)
    const float4* x4 = reinterpret_cast<const float4*>(x + b * D_SZ);
    const float4 x0 = x4[0 * 8 + o];
    const float4 x1 = x4[1 * 8 + o];
    const float4 x2 = x4[2 * 8 + o];
    const float4 x3 = x4[3 * 8 + o];

    const int* idx_b = idx + (size_t)b * K_SZ;
    float wsum = 0.0f;

    #pragma unroll 1
    for (int i = 0; i < KPW; i += RPI) {
        const int myk = k0 + i + r;                  // this lane's row's k
        const int row = (myk == 0) ? y[b] : idx_b[myk];
        const float4* m4 = reinterpret_cast<const float4*>(memory + (size_t)row * D_SZ);

        // 4 independent LDG.128; each instruction touches 4 full 128B lines
        const float4 w0 = m4[0 * 8 + o];
        const float4 w1 = m4[1 * 8 + o];
        const float4 w2 = m4[2 * 8 + o];
        const float4 w3 = m4[3 * 8 + o];

        float acc;
        acc  = w0.x * x0.x + w0.y * x0.y + w0.z * x0.z + w0.w * x0.w;
        acc += w1.x * x1.x + w1.y * x1.y + w1.z * x1.z + w1.w * x1.w;
        acc += w2.x * x2.x + w2.y * x2.y + w2.z * x2.z + w2.w * x2.w;
        acc += w3.x * x3.x + w3.y * x3.y + w3.z * x3.z + w3.w * x3.w;

        // reduce across the 8 lanes of each row (all 4 rows in parallel)
        acc += __shfl_xor_sync(0xffffffffu, acc, 1);
        acc += __shfl_xor_sync(0xffffffffu, acc, 2);
        acc += __shfl_xor_sync(0xffffffffu, acc, 4);

        if (o == 0) {
            const float s = __expf(acc * INV_T);
            out[(size_t)b * K_SZ + myk] = s;
            wsum += s;
        }
    }

    // Block partial: full warp reduce (lanes o!=0 hold 0), then fixed order.
    #pragma unroll
    for (int s = 16; s > 0; s >>= 1)
        wsum += __shfl_xor_sync(0xffffffffu, wsum, s);

    __shared__ float ssum[WARPS];
    __shared__ bool  s_last;
    if (lane == 0) ssum[warp] = wsum;
    __syncthreads();
    if (threadIdx.x == 0) {
        float t = 0.0f;
        #pragma unroll
        for (int w = 0; w < WARPS; w++) t += ssum[w];
        g_partials[blockIdx.y * gridDim.x + blockIdx.x] = t;
        __threadfence();
        const unsigned int tk = atomicAdd(&g_ticket, 1u);
        s_last = (tk == NBLOCKS - 1);
    }
    __syncthreads();

    // Last-arriving block: deterministic double reduce of 2048 partials.
    if (s_last) {
        __shared__ double dsh[THREADS];
        const int t = threadIdx.x;
        double acc = 0.0;
        #pragma unroll
        for (int j = 0; j < NBLOCKS / THREADS; j++)
            acc += (double)g_partials[t + j * THREADS];
        dsh[t] = acc;
        __syncthreads();
        for (int s = THREADS / 2; s > 0; s >>= 1) {
            if (t < s) dsh[t] += dsh[t + s];
            __syncthreads();
        }
        if (t == 0) {
            // Z = (sum / (B*K)) * N ; scale = 1/Z — double avoids fp32
            // overflow (sum ~ 1e31; sum*N would be inf in fp32).
            const double sum = dsh[0];
            g_scale = (float)(((double)B_SZ * (double)K_SZ) /
                              (sum * (double)N_SZ));
            g_ticket = 0u;            // reset for graph replay
            __threadfence();
        }
    }
}

// out: 262144 float4s -> 1024 blocks x 256 threads x 1 float4 (measured 4.8us)
__global__ __launch_bounds__(256)
void nce_norm_kernel(float* __restrict__ out) {
    const float s = g_scale;
    const int i = blockIdx.x * blockDim.x + threadIdx.x;
    float4* o = reinterpret_cast<float4*>(out);
    float4 v = o[i];
    v.x *= s; v.y *= s; v.z *= s; v.w *= s;
    o[i] = v;
}

extern "C" void kernel_launch(void* const* d_in, const int* in_sizes, int n_in,
                              void* d_out, int out_size) {
    const float* x      = (const float*)d_in[0];
    const int*   y      = (const int*)d_in[1];
    const int*   idx    = (const int*)d_in[2];
    const float* memory = (const float*)d_in[3];
    float* out = (float*)d_out;

    dim3 grid1(B_SZ, SPLIT);
    nce_scores_kernel<<<grid1, THREADS>>>(x, y, idx, memory, out);
    const int nvec4 = (B_SZ * K_SZ) / 4;   // 262144
    nce_norm_kernel<<<nvec4 / 256, 256>>>(out);
}